// round 13
// baseline (speedup 1.0000x reference)
#include <cuda_runtime.h>
#include <cuda_fp16.h>
#include <cstdint>

#define HW 4096
#define CD 64
#define BM 64
#define BN 64
#define NT (HW / BN)
#define NB 8
#define RB 72                    // padded row length (16b elems) -> conflict-free ldmatrix
#define RBB (RB * 2)             // row bytes = 144
#define HALF_BYTES (64 * RBB)    // one sub-tile (hi or lo) = 9216B
#define KVBUF (2 * HALF_BYTES)   // hi+lo = 18432B
#define QOFF (2 * KVBUF)         // Q staging region == KV buffer 2 after Q-frag extraction
#define SMEM_TOTAL (3 * KVBUF)   // 55296B -> 4 CTAs/SM
#define L2E 1.4426950408889634f
#define ONES16 0x3C003C00u       // f16x2 (1.0, 1.0)

__device__ __align__(16) __half g_FH[NB * CD * HW];
__device__ __align__(16) __half g_FL[NB * CD * HW];
__device__ float g_negM[NB * HW];   // -(||x_q||^2 + 1) * log2(e)

__device__ __forceinline__ uint32_t smem_u32(const void* p) {
    uint32_t a;
    asm("{ .reg .u64 t; cvta.to.shared.u64 t, %1; cvt.u32.u64 %0, t; }" : "=r"(a) : "l"(p));
    return a;
}
__device__ __forceinline__ void ldsm4(uint32_t addr, uint32_t* r) {
    asm volatile("ldmatrix.sync.aligned.m8n8.x4.shared.b16 {%0,%1,%2,%3}, [%4];"
                 : "=r"(r[0]), "=r"(r[1]), "=r"(r[2]), "=r"(r[3]) : "r"(addr));
}
__device__ __forceinline__ void ldsm4t(uint32_t addr, uint32_t* r) {
    asm volatile("ldmatrix.sync.aligned.m8n8.x4.trans.shared.b16 {%0,%1,%2,%3}, [%4];"
                 : "=r"(r[0]), "=r"(r[1]), "=r"(r[2]), "=r"(r[3]) : "r"(addr));
}
__device__ __forceinline__ void mma_f16(float* d, const uint32_t* a, uint32_t b0, uint32_t b1) {
    asm volatile(
        "mma.sync.aligned.m16n8k16.row.col.f32.f16.f16.f32 "
        "{%0,%1,%2,%3}, {%4,%5,%6,%7}, {%8,%9}, {%0,%1,%2,%3};"
        : "+f"(d[0]), "+f"(d[1]), "+f"(d[2]), "+f"(d[3])
        : "r"(a[0]), "r"(a[1]), "r"(a[2]), "r"(a[3]), "r"(b0), "r"(b1));
}
#define CP16(dst, src) asm volatile("cp.async.cg.shared.global [%0], [%1], 16;" :: "r"(dst), "l"(src))
#define CP_COMMIT()    asm volatile("cp.async.commit_group;" ::: "memory")
#define CP_WAIT1()     asm volatile("cp.async.wait_group 1;" ::: "memory")
#define CP_WAIT2()     asm volatile("cp.async.wait_group 2;" ::: "memory")

__device__ __forceinline__ uint32_t pkf16(float a, float b) {
    uint32_t r;
    asm("cvt.rn.f16x2.f32 %0, %1, %2;" : "=r"(r) : "f"(b), "f"(a));
    return r;
}
__device__ __forceinline__ float ex2(float x) {
    float r;
    asm("ex2.approx.ftz.f32 %0, %1;" : "=f"(r) : "f"(x));
    return r;
}

// ---------------- pre-kernel 1: split X into fp16 hi/lo global arrays ----------------
__global__ __launch_bounds__(256) void convert_kernel(const float* __restrict__ X) {
    size_t i = (size_t)blockIdx.x * 256 + threadIdx.x;
    float4 v = reinterpret_cast<const float4*>(X)[i];
    __half hx = __float2half_rn(v.x), hy = __float2half_rn(v.y);
    __half hz = __float2half_rn(v.z), hw = __float2half_rn(v.w);
    __half lx = __float2half_rn(v.x - __half2float(hx));
    __half ly = __float2half_rn(v.y - __half2float(hy));
    __half lz = __float2half_rn(v.z - __half2float(hz));
    __half lw = __float2half_rn(v.w - __half2float(hw));
    uint2 h, l;
    h.x = (uint32_t)__half_as_ushort(hx) | ((uint32_t)__half_as_ushort(hy) << 16);
    h.y = (uint32_t)__half_as_ushort(hz) | ((uint32_t)__half_as_ushort(hw) << 16);
    l.x = (uint32_t)__half_as_ushort(lx) | ((uint32_t)__half_as_ushort(ly) << 16);
    l.y = (uint32_t)__half_as_ushort(lz) | ((uint32_t)__half_as_ushort(lw) << 16);
    reinterpret_cast<uint2*>(g_FH)[i] = h;
    reinterpret_cast<uint2*>(g_FL)[i] = l;
}

// ---------------- pre-kernel 2: diagonal softmax shift -(||x_q||^2+1)*log2e ----------------
__global__ __launch_bounds__(256) void norm_kernel(const float* __restrict__ X) {
    const int n = blockIdx.y;
    const int q = blockIdx.x * 256 + threadIdx.x;
    const float* Xn = X + (size_t)n * CD * HW;
    float s = 0.f;
#pragma unroll
    for (int c = 0; c < CD; c++) {
        float v = Xn[c * HW + q];
        s = fmaf(v, v, s);
    }
    g_negM[n * HW + q] = -(s + 1.0f) * L2E;
}

// ---------------- main attention kernel ----------------
__global__ __launch_bounds__(128, 4) void attn_mma(float* __restrict__ out) {
    extern __shared__ __align__(128) char SM[];
    const uint32_t smb = smem_u32(SM);

    const int n = blockIdx.y;
    const int q0 = blockIdx.x * BM;
    const int tid = threadIdx.x;
    const int lane = tid & 31;
    const int wid = tid >> 5;          // warp owns q rows wid*16 .. +15
    const int g = lane >> 2, tq = lane & 3;
    const int r8 = lane & 7, sel = lane >> 3;

    const char* FHn = (const char*)(g_FH + (size_t)n * CD * HW);
    const char* FLn = (const char*)(g_FL + (size_t)n * CD * HW);

    auto stage = [&](uint32_t bufoff, int col0) {
#pragma unroll
        for (int i = 0; i < 8; i++) {
            int idx = i * 128 + tid;
            int half = idx >> 9;
            int c = (idx >> 3) & 63;
            int ch = idx & 7;
            const char* base = half ? FLn : FHn;
            const char* src = base + ((size_t)c * HW + col0 + ch * 8) * 2;
            uint32_t dst = smb + bufoff + half * HALF_BYTES + c * RBB + ch * 16;
            CP16(dst, src);
        }
    };

    // prologue: Q -> buf2(QOFF), KV tiles 0,1 -> buf0,buf1
    stage(QOFF, q0);     CP_COMMIT();
    stage(0, 0);         CP_COMMIT();
    stage(KVBUF, BN);    CP_COMMIT();
    CP_WAIT2();          // Q resident
    __syncthreads();

    // ---- Q A-fragments (trans ldmatrix from [c][q] layout), hi+lo fp16 ----
    uint32_t qh[4][4], ql[4][4];
    {
        const uint32_t qb = smb + QOFF;
        const uint32_t lo = ((sel >> 1) * 8 + r8) * RBB + (wid * 16 + (sel & 1) * 8) * 2;
#pragma unroll
        for (int ch = 0; ch < 4; ch++) {
            ldsm4t(qb + ch * 16 * RBB + lo, qh[ch]);
            ldsm4t(qb + HALF_BYTES + ch * 16 * RBB + lo, ql[ch]);
        }
    }

    const int row_a = wid * 16 + g, row_b = row_a + 8;
    const float negMa = g_negM[n * HW + q0 + row_a];
    const float negMb = g_negM[n * HW + q0 + row_b];

    float o[8][4];
#pragma unroll
    for (int j = 0; j < 8; j++)
#pragma unroll
        for (int r = 0; r < 4; r++) o[j][r] = 0.f;
    float ol[4] = {0.f, 0.f, 0.f, 0.f};   // l accumulator via ones-column MMA

    const uint32_t g1off = ((sel & 1) * 8 + r8) * RBB + ((sel >> 1) * 8) * 2;
    const uint32_t g2off = ((sel >> 1) * 8 + r8) * RBB + ((sel & 1) * 8) * 2;

    for (int t = 0; t < NT; t++) {
        CP_WAIT1();          // tile t resident (t+1 may still be in flight)
        __syncthreads();     // visibility of tile t + all warps done with buf[(t+2)%3]
        if (t + 2 < NT) stage(((t + 2) % 3) * KVBUF, (t + 2) * BN);
        CP_COMMIT();         // commit every iteration (keeps group accounting fixed)
        const uint32_t vb = smb + ((uint32_t)(t % 3)) * KVBUF;

        // ---- gemm1: S(16x64) = Q Kt, fp16 3 split passes ----
        float s[8][4];
#pragma unroll
        for (int j = 0; j < 8; j++)
#pragma unroll
            for (int r = 0; r < 4; r++) s[j][r] = 0.f;
#pragma unroll
        for (int ch = 0; ch < 4; ch++) {
            const uint32_t base = vb + g1off + ch * 16 * RBB;
#pragma unroll
            for (int kp = 0; kp < 2; kp++) {
                const uint32_t ka = base + (2 * kp) * 32;
                const uint32_t kb = ka + 32;
                uint32_t bh0[4], bl0[4], bh1[4], bl1[4];
                ldsm4t(ka, bh0);
                ldsm4t(ka + HALF_BYTES, bl0);
                ldsm4t(kb, bh1);
                ldsm4t(kb + HALF_BYTES, bl1);
                float* s0 = s[4 * kp], * s1 = s[4 * kp + 1];
                float* s2 = s[4 * kp + 2], * s3 = s[4 * kp + 3];
                mma_f16(s0, qh[ch], bh0[0], bh0[1]);
                mma_f16(s1, qh[ch], bh0[2], bh0[3]);
                mma_f16(s2, qh[ch], bh1[0], bh1[1]);
                mma_f16(s3, qh[ch], bh1[2], bh1[3]);
                mma_f16(s0, qh[ch], bl0[0], bl0[1]);
                mma_f16(s1, qh[ch], bl0[2], bl0[3]);
                mma_f16(s2, qh[ch], bl1[0], bl1[1]);
                mma_f16(s3, qh[ch], bl1[2], bl1[3]);
                mma_f16(s0, ql[ch], bh0[0], bh0[1]);
                mma_f16(s1, ql[ch], bh0[2], bh0[3]);
                mma_f16(s2, ql[ch], bh1[0], bh1[1]);
                mma_f16(s3, ql[ch], bh1[2], bh1[3]);
            }
        }

        // ---- static-shift softmax: P = exp2(S*log2e - M'), no max, no rescale, no l adds ----
        uint32_t pf[4][4];
#pragma unroll
        for (int kc = 0; kc < 4; kc++) {
            float e0 = ex2(fmaf(s[2 * kc][0], L2E, negMa));
            float e1 = ex2(fmaf(s[2 * kc][1], L2E, negMa));
            float e2 = ex2(fmaf(s[2 * kc][2], L2E, negMb));
            float e3 = ex2(fmaf(s[2 * kc][3], L2E, negMb));
            float e4 = ex2(fmaf(s[2 * kc + 1][0], L2E, negMa));
            float e5 = ex2(fmaf(s[2 * kc + 1][1], L2E, negMa));
            float e6 = ex2(fmaf(s[2 * kc + 1][2], L2E, negMb));
            float e7 = ex2(fmaf(s[2 * kc + 1][3], L2E, negMb));
            pf[kc][0] = pkf16(e0, e1);
            pf[kc][1] = pkf16(e2, e3);
            pf[kc][2] = pkf16(e4, e5);
            pf[kc][3] = pkf16(e6, e7);
        }

        // ---- gemm2: O(16x64) += P V (fp16), plus l += P * ones ----
#pragma unroll
        for (int kc = 0; kc < 4; kc++) {
#pragma unroll
            for (int mp = 0; mp < 2; mp++) {
                const uint32_t ba = vb + g2off + (2 * mp) * 16 * RBB + kc * 32;
                const uint32_t bb = ba + 16 * RBB;
                uint32_t bfa[4], bfb[4];
                ldsm4(ba, bfa);
                ldsm4(bb, bfb);
                mma_f16(o[4 * mp], pf[kc], bfa[0], bfa[1]);
                mma_f16(o[4 * mp + 1], pf[kc], bfa[2], bfa[3]);
                mma_f16(o[4 * mp + 2], pf[kc], bfb[0], bfb[1]);
                mma_f16(o[4 * mp + 3], pf[kc], bfb[2], bfb[3]);
            }
            mma_f16(ol, pf[kc], ONES16, ONES16);   // row sums (every lane gets them)
        }
    }

    // ---- epilogue: ol[0]=l(row_a), ol[2]=l(row_b) in every lane -> normalize + store ----
    const float ia = 1.f / ol[0], ib = 1.f / ol[2];
    float* On = out + (size_t)n * CD * HW + q0;
#pragma unroll
    for (int j = 0; j < 8; j++) {
        int cb2 = j * 8 + 2 * tq;
        On[(size_t)cb2 * HW + row_a] = o[j][0] * ia;
        On[(size_t)(cb2 + 1) * HW + row_a] = o[j][1] * ia;
        On[(size_t)cb2 * HW + row_b] = o[j][2] * ib;
        On[(size_t)(cb2 + 1) * HW + row_b] = o[j][3] * ib;
    }
}

extern "C" void kernel_launch(void* const* d_in, const int* in_sizes, int n_in,
                              void* d_out, int out_size) {
    const float* X = (const float*)d_in[0];
    float* out = (float*)d_out;
    cudaFuncSetAttribute(attn_mma, cudaFuncAttributeMaxDynamicSharedMemorySize, SMEM_TOTAL);
    convert_kernel<<<(NB * CD * HW / 4) / 256, 256>>>(X);
    norm_kernel<<<dim3(HW / 256, NB), 256>>>(X);
    attn_mma<<<dim3(HW / BM, NB), 128, SMEM_TOTAL>>>(out);
}

// round 14
// speedup vs baseline: 1.0002x; 1.0002x over previous
#include <cuda_runtime.h>
#include <cuda_fp16.h>
#include <cstdint>

#define HW 4096
#define CD 64
#define BM 64
#define BN 64
#define NT (HW / BN)
#define NB 8
#define RB 72                    // padded row length (16b elems) -> conflict-free ldmatrix
#define RBB (RB * 2)             // row bytes = 144
#define HALF_BYTES (64 * RBB)    // one sub-tile (hi or lo) = 9216B
#define KVBUF (2 * HALF_BYTES)   // hi+lo = 18432B
#define QOFF (2 * KVBUF)         // Q staging region == KV buffer 2 after Q-frag extraction
#define SMEM_TOTAL (3 * KVBUF)   // 55296B -> 4 CTAs/SM
#define L2E 1.4426950408889634f
#define ONES16 0x3C003C00u       // f16x2 (1.0, 1.0)

__device__ __align__(16) __half g_FH[NB * CD * HW];
__device__ __align__(16) __half g_FL[NB * CD * HW];
__device__ float g_negM[NB * HW];   // -(||x_q||^2 + 1) * log2(e)

__device__ __forceinline__ uint32_t smem_u32(const void* p) {
    uint32_t a;
    asm("{ .reg .u64 t; cvta.to.shared.u64 t, %1; cvt.u32.u64 %0, t; }" : "=r"(a) : "l"(p));
    return a;
}
__device__ __forceinline__ void ldsm4(uint32_t addr, uint32_t* r) {
    asm volatile("ldmatrix.sync.aligned.m8n8.x4.shared.b16 {%0,%1,%2,%3}, [%4];"
                 : "=r"(r[0]), "=r"(r[1]), "=r"(r[2]), "=r"(r[3]) : "r"(addr));
}
__device__ __forceinline__ void ldsm4t(uint32_t addr, uint32_t* r) {
    asm volatile("ldmatrix.sync.aligned.m8n8.x4.trans.shared.b16 {%0,%1,%2,%3}, [%4];"
                 : "=r"(r[0]), "=r"(r[1]), "=r"(r[2]), "=r"(r[3]) : "r"(addr));
}
__device__ __forceinline__ void mma_f16(float* d, const uint32_t* a, uint32_t b0, uint32_t b1) {
    asm volatile(
        "mma.sync.aligned.m16n8k16.row.col.f32.f16.f16.f32 "
        "{%0,%1,%2,%3}, {%4,%5,%6,%7}, {%8,%9}, {%0,%1,%2,%3};"
        : "+f"(d[0]), "+f"(d[1]), "+f"(d[2]), "+f"(d[3])
        : "r"(a[0]), "r"(a[1]), "r"(a[2]), "r"(a[3]), "r"(b0), "r"(b1));
}
#define CP16(dst, src) asm volatile("cp.async.cg.shared.global [%0], [%1], 16;" :: "r"(dst), "l"(src))
#define CP_COMMIT()    asm volatile("cp.async.commit_group;" ::: "memory")
#define CP_WAIT1()     asm volatile("cp.async.wait_group 1;" ::: "memory")
#define CP_WAIT2()     asm volatile("cp.async.wait_group 2;" ::: "memory")

// pack two f32 -> f16x2, a in LOW half
__device__ __forceinline__ uint32_t pkf16(float a, float b) {
    uint32_t r;
    asm("cvt.rn.f16x2.f32 %0, %1, %2;" : "=r"(r) : "f"(b), "f"(a));
    return r;
}
// paired fp16 exp2: one MUFU op for two values, result is a ready P fragment half
__device__ __forceinline__ uint32_t ex2h2(uint32_t packed_args) {
    uint32_t r;
    asm("ex2.approx.f16x2 %0, %1;" : "=r"(r) : "r"(packed_args));
    return r;
}

// ---------------- pre-kernel 1: split X into fp16 hi/lo global arrays ----------------
__global__ __launch_bounds__(256) void convert_kernel(const float* __restrict__ X) {
    size_t i = (size_t)blockIdx.x * 256 + threadIdx.x;
    float4 v = reinterpret_cast<const float4*>(X)[i];
    __half hx = __float2half_rn(v.x), hy = __float2half_rn(v.y);
    __half hz = __float2half_rn(v.z), hw = __float2half_rn(v.w);
    __half lx = __float2half_rn(v.x - __half2float(hx));
    __half ly = __float2half_rn(v.y - __half2float(hy));
    __half lz = __float2half_rn(v.z - __half2float(hz));
    __half lw = __float2half_rn(v.w - __half2float(hw));
    uint2 h, l;
    h.x = (uint32_t)__half_as_ushort(hx) | ((uint32_t)__half_as_ushort(hy) << 16);
    h.y = (uint32_t)__half_as_ushort(hz) | ((uint32_t)__half_as_ushort(hw) << 16);
    l.x = (uint32_t)__half_as_ushort(lx) | ((uint32_t)__half_as_ushort(ly) << 16);
    l.y = (uint32_t)__half_as_ushort(lz) | ((uint32_t)__half_as_ushort(lw) << 16);
    reinterpret_cast<uint2*>(g_FH)[i] = h;
    reinterpret_cast<uint2*>(g_FL)[i] = l;
}

// ---------------- pre-kernel 2: diagonal softmax shift -(||x_q||^2+1)*log2e ----------------
__global__ __launch_bounds__(256) void norm_kernel(const float* __restrict__ X) {
    const int n = blockIdx.y;
    const int q = blockIdx.x * 256 + threadIdx.x;
    const float* Xn = X + (size_t)n * CD * HW;
    float s = 0.f;
#pragma unroll
    for (int c = 0; c < CD; c++) {
        float v = Xn[c * HW + q];
        s = fmaf(v, v, s);
    }
    g_negM[n * HW + q] = -(s + 1.0f) * L2E;
}

// ---------------- main attention kernel ----------------
__global__ __launch_bounds__(128, 4) void attn_mma(float* __restrict__ out) {
    extern __shared__ __align__(128) char SM[];
    const uint32_t smb = smem_u32(SM);

    const int n = blockIdx.y;
    const int q0 = blockIdx.x * BM;
    const int tid = threadIdx.x;
    const int lane = tid & 31;
    const int wid = tid >> 5;          // warp owns q rows wid*16 .. +15
    const int g = lane >> 2, tq = lane & 3;
    const int r8 = lane & 7, sel = lane >> 3;

    const char* FHn = (const char*)(g_FH + (size_t)n * CD * HW);
    const char* FLn = (const char*)(g_FL + (size_t)n * CD * HW);

    auto stage = [&](uint32_t bufoff, int col0) {
#pragma unroll
        for (int i = 0; i < 8; i++) {
            int idx = i * 128 + tid;
            int half = idx >> 9;
            int c = (idx >> 3) & 63;
            int ch = idx & 7;
            const char* base = half ? FLn : FHn;
            const char* src = base + ((size_t)c * HW + col0 + ch * 8) * 2;
            uint32_t dst = smb + bufoff + half * HALF_BYTES + c * RBB + ch * 16;
            CP16(dst, src);
        }
    };

    // prologue: Q -> buf2(QOFF), KV tiles 0,1 -> buf0,buf1
    stage(QOFF, q0);     CP_COMMIT();
    stage(0, 0);         CP_COMMIT();
    stage(KVBUF, BN);    CP_COMMIT();
    CP_WAIT2();          // Q resident
    __syncthreads();

    // ---- Q A-fragments (trans ldmatrix from [c][q] layout), hi+lo fp16 ----
    uint32_t qh[4][4], ql[4][4];
    {
        const uint32_t qb = smb + QOFF;
        const uint32_t lo = ((sel >> 1) * 8 + r8) * RBB + (wid * 16 + (sel & 1) * 8) * 2;
#pragma unroll
        for (int ch = 0; ch < 4; ch++) {
            ldsm4t(qb + ch * 16 * RBB + lo, qh[ch]);
            ldsm4t(qb + HALF_BYTES + ch * 16 * RBB + lo, ql[ch]);
        }
    }

    const int row_a = wid * 16 + g, row_b = row_a + 8;
    const float negMa = g_negM[n * HW + q0 + row_a];
    const float negMb = g_negM[n * HW + q0 + row_b];

    float o[8][4];
#pragma unroll
    for (int j = 0; j < 8; j++)
#pragma unroll
        for (int r = 0; r < 4; r++) o[j][r] = 0.f;
    float ol[4] = {0.f, 0.f, 0.f, 0.f};   // l accumulator via ones-column MMA

    const uint32_t g1off = ((sel & 1) * 8 + r8) * RBB + ((sel >> 1) * 8) * 2;
    const uint32_t g2off = ((sel >> 1) * 8 + r8) * RBB + ((sel & 1) * 8) * 2;

    for (int t = 0; t < NT; t++) {
        CP_WAIT1();          // tile t resident (t+1 may still be in flight)
        __syncthreads();     // visibility of tile t + all warps done with buf[(t+2)%3]
        if (t + 2 < NT) stage(((t + 2) % 3) * KVBUF, (t + 2) * BN);
        CP_COMMIT();
        const uint32_t vb = smb + ((uint32_t)(t % 3)) * KVBUF;

        // ---- gemm1: S(16x64) = Q Kt, fp16 3 split passes ----
        float s[8][4];
#pragma unroll
        for (int j = 0; j < 8; j++)
#pragma unroll
            for (int r = 0; r < 4; r++) s[j][r] = 0.f;
#pragma unroll
        for (int ch = 0; ch < 4; ch++) {
            const uint32_t base = vb + g1off + ch * 16 * RBB;
#pragma unroll
            for (int kp = 0; kp < 2; kp++) {
                const uint32_t ka = base + (2 * kp) * 32;
                const uint32_t kb = ka + 32;
                uint32_t bh0[4], bl0[4], bh1[4], bl1[4];
                ldsm4t(ka, bh0);
                ldsm4t(ka + HALF_BYTES, bl0);
                ldsm4t(kb, bh1);
                ldsm4t(kb + HALF_BYTES, bl1);
                float* s0 = s[4 * kp], * s1 = s[4 * kp + 1];
                float* s2 = s[4 * kp + 2], * s3 = s[4 * kp + 3];
                mma_f16(s0, qh[ch], bh0[0], bh0[1]);
                mma_f16(s1, qh[ch], bh0[2], bh0[3]);
                mma_f16(s2, qh[ch], bh1[0], bh1[1]);
                mma_f16(s3, qh[ch], bh1[2], bh1[3]);
                mma_f16(s0, qh[ch], bl0[0], bl0[1]);
                mma_f16(s1, qh[ch], bl0[2], bl0[3]);
                mma_f16(s2, qh[ch], bl1[0], bl1[1]);
                mma_f16(s3, qh[ch], bl1[2], bl1[3]);
                mma_f16(s0, ql[ch], bh0[0], bh0[1]);
                mma_f16(s1, ql[ch], bh0[2], bh0[3]);
                mma_f16(s2, ql[ch], bh1[0], bh1[1]);
                mma_f16(s3, ql[ch], bh1[2], bh1[3]);
            }
        }

        // ---- static-shift softmax: args in f32, pack to f16x2, paired f16 ex2 ----
        // pf[kc][h] = ex2.f16x2( pack( S*log2e - M ) )  -- output IS the P fragment
        uint32_t pf[4][4];
#pragma unroll
        for (int kc = 0; kc < 4; kc++) {
            float a0 = fmaf(s[2 * kc][0], L2E, negMa);
            float a1 = fmaf(s[2 * kc][1], L2E, negMa);
            float a2 = fmaf(s[2 * kc][2], L2E, negMb);
            float a3 = fmaf(s[2 * kc][3], L2E, negMb);
            float a4 = fmaf(s[2 * kc + 1][0], L2E, negMa);
            float a5 = fmaf(s[2 * kc + 1][1], L2E, negMa);
            float a6 = fmaf(s[2 * kc + 1][2], L2E, negMb);
            float a7 = fmaf(s[2 * kc + 1][3], L2E, negMb);
            pf[kc][0] = ex2h2(pkf16(a0, a1));
            pf[kc][1] = ex2h2(pkf16(a2, a3));
            pf[kc][2] = ex2h2(pkf16(a4, a5));
            pf[kc][3] = ex2h2(pkf16(a6, a7));
        }

        // ---- gemm2: O(16x64) += P V (fp16), plus l += P * ones ----
#pragma unroll
        for (int kc = 0; kc < 4; kc++) {
#pragma unroll
            for (int mp = 0; mp < 2; mp++) {
                const uint32_t ba = vb + g2off + (2 * mp) * 16 * RBB + kc * 32;
                const uint32_t bb = ba + 16 * RBB;
                uint32_t bfa[4], bfb[4];
                ldsm4(ba, bfa);
                ldsm4(bb, bfb);
                mma_f16(o[4 * mp], pf[kc], bfa[0], bfa[1]);
                mma_f16(o[4 * mp + 1], pf[kc], bfa[2], bfa[3]);
                mma_f16(o[4 * mp + 2], pf[kc], bfb[0], bfb[1]);
                mma_f16(o[4 * mp + 3], pf[kc], bfb[2], bfb[3]);
            }
            mma_f16(ol, pf[kc], ONES16, ONES16);   // row sums of fp16 P
        }
    }

    // ---- epilogue: ol[0]=l(row_a), ol[2]=l(row_b) in every lane -> normalize + store ----
    const float ia = 1.f / ol[0], ib = 1.f / ol[2];
    float* On = out + (size_t)n * CD * HW + q0;
#pragma unroll
    for (int j = 0; j < 8; j++) {
        int cb2 = j * 8 + 2 * tq;
        On[(size_t)cb2 * HW + row_a] = o[j][0] * ia;
        On[(size_t)(cb2 + 1) * HW + row_a] = o[j][1] * ia;
        On[(size_t)cb2 * HW + row_b] = o[j][2] * ib;
        On[(size_t)(cb2 + 1) * HW + row_b] = o[j][3] * ib;
    }
}

extern "C" void kernel_launch(void* const* d_in, const int* in_sizes, int n_in,
                              void* d_out, int out_size) {
    const float* X = (const float*)d_in[0];
    float* out = (float*)d_out;
    cudaFuncSetAttribute(attn_mma, cudaFuncAttributeMaxDynamicSharedMemorySize, SMEM_TOTAL);
    convert_kernel<<<(NB * CD * HW / 4) / 256, 256>>>(X);
    norm_kernel<<<dim3(HW / 256, NB), 256>>>(X);
    attn_mma<<<dim3(HW / BM, NB), 128, SMEM_TOTAL>>>(out);
}

// round 15
// speedup vs baseline: 1.0235x; 1.0234x over previous
#include <cuda_runtime.h>
#include <cuda_fp16.h>
#include <cstdint>

#define HW 4096
#define CD 64
#define BM 64
#define BN 64
#define NB 8
#define NQT (HW / BM)            // 64 q-tiles per batch
#define TOTU (NB * NQT * 64)     // 32768 (q-tile, kv-tile) units
#define NCTA 592                 // 4 x 148 -> exactly one uniform wave
#define RB 72
#define RBB (RB * 2)             // 144
#define HALF_BYTES (64 * RBB)    // 9216
#define KVBUF (2 * HALF_BYTES)   // 18432
#define SMEM_TOTAL (3 * KVBUF)   // 55296 -> 4 CTAs/SM
#define L2E 1.4426950408889634f

__device__ __align__(16) __half g_FH[NB * CD * HW];
__device__ __align__(16) __half g_FL[NB * CD * HW];
__device__ float g_negM[NB * HW];   // -(||x_q||^2 + 1) * log2(e)
__device__ float g_lacc[NB * HW];   // softmax denominator accumulator

__device__ __forceinline__ uint32_t smem_u32(const void* p) {
    uint32_t a;
    asm("{ .reg .u64 t; cvta.to.shared.u64 t, %1; cvt.u32.u64 %0, t; }" : "=r"(a) : "l"(p));
    return a;
}
__device__ __forceinline__ void ldsm4(uint32_t addr, uint32_t* r) {
    asm volatile("ldmatrix.sync.aligned.m8n8.x4.shared.b16 {%0,%1,%2,%3}, [%4];"
                 : "=r"(r[0]), "=r"(r[1]), "=r"(r[2]), "=r"(r[3]) : "r"(addr));
}
__device__ __forceinline__ void ldsm4t(uint32_t addr, uint32_t* r) {
    asm volatile("ldmatrix.sync.aligned.m8n8.x4.trans.shared.b16 {%0,%1,%2,%3}, [%4];"
                 : "=r"(r[0]), "=r"(r[1]), "=r"(r[2]), "=r"(r[3]) : "r"(addr));
}
__device__ __forceinline__ void mma_f16(float* d, const uint32_t* a, uint32_t b0, uint32_t b1) {
    asm volatile(
        "mma.sync.aligned.m16n8k16.row.col.f32.f16.f16.f32 "
        "{%0,%1,%2,%3}, {%4,%5,%6,%7}, {%8,%9}, {%0,%1,%2,%3};"
        : "+f"(d[0]), "+f"(d[1]), "+f"(d[2]), "+f"(d[3])
        : "r"(a[0]), "r"(a[1]), "r"(a[2]), "r"(a[3]), "r"(b0), "r"(b1));
}
#define CP16(dst, src) asm volatile("cp.async.cg.shared.global [%0], [%1], 16;" :: "r"(dst), "l"(src))
#define CP_COMMIT()    asm volatile("cp.async.commit_group;" ::: "memory")
#define CP_WAIT0()     asm volatile("cp.async.wait_group 0;" ::: "memory")
#define CP_WAIT1()     asm volatile("cp.async.wait_group 1;" ::: "memory")

__device__ __forceinline__ uint32_t pkf16(float a, float b) {
    uint32_t r;
    asm("cvt.rn.f16x2.f32 %0, %1, %2;" : "=r"(r) : "f"(b), "f"(a));
    return r;
}
__device__ __forceinline__ float ex2(float x) {
    float r;
    asm("ex2.approx.ftz.f32 %0, %1;" : "=f"(r) : "f"(x));
    return r;
}

// ---------------- pre-kernel 0: zero out-accumulator and l-accumulator ----------------
__global__ __launch_bounds__(256) void zero_kernel(float* __restrict__ out) {
    int b = blockIdx.x;
    int i = b * 256 + threadIdx.x;
    if (b < 2048) {
        reinterpret_cast<float4*>(out)[i] = make_float4(0.f, 0.f, 0.f, 0.f);
    } else {
        int j = i - 2048 * 256;
        reinterpret_cast<float4*>(g_lacc)[j] = make_float4(0.f, 0.f, 0.f, 0.f);
    }
}

// ---------------- pre-kernel 1: split X into fp16 hi/lo ----------------
__global__ __launch_bounds__(256) void convert_kernel(const float* __restrict__ X) {
    size_t i = (size_t)blockIdx.x * 256 + threadIdx.x;
    float4 v = reinterpret_cast<const float4*>(X)[i];
    __half hx = __float2half_rn(v.x), hy = __float2half_rn(v.y);
    __half hz = __float2half_rn(v.z), hw = __float2half_rn(v.w);
    __half lx = __float2half_rn(v.x - __half2float(hx));
    __half ly = __float2half_rn(v.y - __half2float(hy));
    __half lz = __float2half_rn(v.z - __half2float(hz));
    __half lw = __float2half_rn(v.w - __half2float(hw));
    uint2 h, l;
    h.x = (uint32_t)__half_as_ushort(hx) | ((uint32_t)__half_as_ushort(hy) << 16);
    h.y = (uint32_t)__half_as_ushort(hz) | ((uint32_t)__half_as_ushort(hw) << 16);
    l.x = (uint32_t)__half_as_ushort(lx) | ((uint32_t)__half_as_ushort(ly) << 16);
    l.y = (uint32_t)__half_as_ushort(lz) | ((uint32_t)__half_as_ushort(lw) << 16);
    reinterpret_cast<uint2*>(g_FH)[i] = h;
    reinterpret_cast<uint2*>(g_FL)[i] = l;
}

// ---------------- pre-kernel 2: diagonal softmax shift ----------------
__global__ __launch_bounds__(256) void norm_kernel(const float* __restrict__ X) {
    const int n = blockIdx.y;
    const int q = blockIdx.x * 256 + threadIdx.x;
    const float* Xn = X + (size_t)n * CD * HW;
    float s = 0.f;
#pragma unroll
    for (int c = 0; c < CD; c++) {
        float v = Xn[c * HW + q];
        s = fmaf(v, v, s);
    }
    g_negM[n * HW + q] = -(s + 1.0f) * L2E;
}

// ---------------- post-kernel: normalize ----------------
__global__ __launch_bounds__(256) void final_kernel(float* __restrict__ out) {
    int idx = blockIdx.x * 256 + threadIdx.x;       // over NB*CD*HW
    int q = idx & (HW - 1);
    int n = idx >> 18;                               // CD*HW = 2^18
    out[idx] *= 1.0f / g_lacc[n * HW + q];
}

// ---------------- main attention kernel: 592 uniform tasks ----------------
__global__ __launch_bounds__(128, 4) void attn_mma(float* __restrict__ out) {
    extern __shared__ __align__(128) char SM[];
    const uint32_t smb = smem_u32(SM);

    const int tid = threadIdx.x;
    const int lane = tid & 31;
    const int wid = tid >> 5;
    const int g = lane >> 2, tq = lane & 3;
    const int r8 = lane & 7, sel = lane >> 3;

    const uint32_t g1off = ((sel & 1) * 8 + r8) * RBB + ((sel >> 1) * 8) * 2;
    const uint32_t g2off = ((sel >> 1) * 8 + r8) * RBB + ((sel & 1) * 8) * 2;

    const int k = blockIdx.x;
    int u = (k * 2048) / 37;                 // unit range [u, uend)
    const int uend = ((k + 1) * 2048) / 37;

    while (u < uend) {
        const int qt = u >> 6;               // global q-tile 0..511
        const int n = qt >> 6;
        const int q0 = (qt & 63) * BM;
        const int kv0 = u & 63;
        const int kvend = min(uend - (qt << 6), 64);
        const int cnt = kvend - kv0;

        const char* FHn = (const char*)(g_FH + (size_t)n * CD * HW);
        const char* FLn = (const char*)(g_FL + (size_t)n * CD * HW);

        auto stage = [&](uint32_t bufoff, int col0) {
#pragma unroll
            for (int i = 0; i < 8; i++) {
                int idx = i * 128 + tid;
                int half = idx >> 9;
                int c = (idx >> 3) & 63;
                int ch = idx & 7;
                const char* base = half ? FLn : FHn;
                const char* src = base + ((size_t)c * HW + col0 + ch * 8) * 2;
                uint32_t dst = smb + bufoff + half * HALF_BYTES + c * RBB + ch * 16;
                CP16(dst, src);
            }
        };

        // ---- segment prologue: Q into buf2, extract fragments ----
        __syncthreads();                     // previous segment's reads complete
        stage(2 * KVBUF, q0);
        CP_COMMIT();
        CP_WAIT0();
        __syncthreads();
        uint32_t qh[4][4], ql[4][4];
        {
            const uint32_t qb = smb + 2 * KVBUF;
            const uint32_t lo = ((sel >> 1) * 8 + r8) * RBB + (wid * 16 + (sel & 1) * 8) * 2;
#pragma unroll
            for (int ch = 0; ch < 4; ch++) {
                ldsm4t(qb + ch * 16 * RBB + lo, qh[ch]);
                ldsm4t(qb + HALF_BYTES + ch * 16 * RBB + lo, ql[ch]);
            }
        }
        const int row_a = wid * 16 + g, row_b = row_a + 8;
        const float negMa = g_negM[n * HW + q0 + row_a];
        const float negMb = g_negM[n * HW + q0 + row_b];

        float o[8][4];
#pragma unroll
        for (int j = 0; j < 8; j++)
#pragma unroll
            for (int r = 0; r < 4; r++) o[j][r] = 0.f;
        float la = 0.f, lb = 0.f;

        // prefetch first two KV tiles of the segment
        stage(0, (kv0 + 0) * BN);
        CP_COMMIT();
        if (cnt > 1) stage(KVBUF, (kv0 + 1) * BN);
        CP_COMMIT();

        for (int i = 0; i < cnt; i++) {
            CP_WAIT1();
            __syncthreads();                 // tile i visible; buf (i+2)%3 free
            if (i + 2 < cnt) stage(((i + 2) % 3) * KVBUF, (kv0 + i + 2) * BN);
            CP_COMMIT();
            const uint32_t vb = smb + ((uint32_t)(i % 3)) * KVBUF;

            // ---- gemm1: S(16x64) = Q Kt, fp16 3 split passes ----
            float s[8][4];
#pragma unroll
            for (int j = 0; j < 8; j++)
#pragma unroll
                for (int r = 0; r < 4; r++) s[j][r] = 0.f;
#pragma unroll
            for (int ch = 0; ch < 4; ch++) {
                const uint32_t base = vb + g1off + ch * 16 * RBB;
#pragma unroll
                for (int kp = 0; kp < 2; kp++) {
                    const uint32_t ka = base + (2 * kp) * 32;
                    const uint32_t kb = ka + 32;
                    uint32_t bh0[4], bl0[4], bh1[4], bl1[4];
                    ldsm4t(ka, bh0);
                    ldsm4t(ka + HALF_BYTES, bl0);
                    ldsm4t(kb, bh1);
                    ldsm4t(kb + HALF_BYTES, bl1);
                    float* s0 = s[4 * kp], * s1 = s[4 * kp + 1];
                    float* s2 = s[4 * kp + 2], * s3 = s[4 * kp + 3];
                    mma_f16(s0, qh[ch], bh0[0], bh0[1]);
                    mma_f16(s1, qh[ch], bh0[2], bh0[3]);
                    mma_f16(s2, qh[ch], bh1[0], bh1[1]);
                    mma_f16(s3, qh[ch], bh1[2], bh1[3]);
                    mma_f16(s0, qh[ch], bl0[0], bl0[1]);
                    mma_f16(s1, qh[ch], bl0[2], bl0[3]);
                    mma_f16(s2, qh[ch], bl1[0], bl1[1]);
                    mma_f16(s3, qh[ch], bl1[2], bl1[3]);
                    mma_f16(s0, ql[ch], bh0[0], bh0[1]);
                    mma_f16(s1, ql[ch], bh0[2], bh0[3]);
                    mma_f16(s2, ql[ch], bh1[0], bh1[1]);
                    mma_f16(s3, ql[ch], bh1[2], bh1[3]);
                }
            }

            // ---- static-shift softmax ----
            uint32_t pf[4][4];
#pragma unroll
            for (int kc = 0; kc < 4; kc++) {
                float e0 = ex2(fmaf(s[2 * kc][0], L2E, negMa));
                float e1 = ex2(fmaf(s[2 * kc][1], L2E, negMa));
                float e2 = ex2(fmaf(s[2 * kc][2], L2E, negMb));
                float e3 = ex2(fmaf(s[2 * kc][3], L2E, negMb));
                float e4 = ex2(fmaf(s[2 * kc + 1][0], L2E, negMa));
                float e5 = ex2(fmaf(s[2 * kc + 1][1], L2E, negMa));
                float e6 = ex2(fmaf(s[2 * kc + 1][2], L2E, negMb));
                float e7 = ex2(fmaf(s[2 * kc + 1][3], L2E, negMb));
                la += e0 + e1 + e4 + e5;
                lb += e2 + e3 + e6 + e7;
                pf[kc][0] = pkf16(e0, e1);
                pf[kc][1] = pkf16(e2, e3);
                pf[kc][2] = pkf16(e4, e5);
                pf[kc][3] = pkf16(e6, e7);
            }

            // ---- gemm2: O += P V ----
#pragma unroll
            for (int kc = 0; kc < 4; kc++) {
#pragma unroll
                for (int mp = 0; mp < 2; mp++) {
                    const uint32_t ba = vb + g2off + (2 * mp) * 16 * RBB + kc * 32;
                    const uint32_t bb = ba + 16 * RBB;
                    uint32_t bfa[4], bfb[4];
                    ldsm4(ba, bfa);
                    ldsm4(bb, bfb);
                    mma_f16(o[4 * mp], pf[kc], bfa[0], bfa[1]);
                    mma_f16(o[4 * mp + 1], pf[kc], bfa[2], bfa[3]);
                    mma_f16(o[4 * mp + 2], pf[kc], bfb[0], bfb[1]);
                    mma_f16(o[4 * mp + 3], pf[kc], bfb[2], bfb[3]);
                }
            }
        }
        CP_WAIT0();                          // drain before next segment reuses buffers

        // ---- flush partial O and l (additive under the static shift) ----
        la += __shfl_xor_sync(~0u, la, 1);
        la += __shfl_xor_sync(~0u, la, 2);
        lb += __shfl_xor_sync(~0u, lb, 1);
        lb += __shfl_xor_sync(~0u, lb, 2);
        if (tq == 0) {
            atomicAdd(&g_lacc[n * HW + q0 + row_a], la);
            atomicAdd(&g_lacc[n * HW + q0 + row_b], lb);
        }
        float* On = out + (size_t)n * CD * HW + q0;
#pragma unroll
        for (int j = 0; j < 8; j++) {
            int cb2 = j * 8 + 2 * tq;
            atomicAdd(&On[(size_t)cb2 * HW + row_a], o[j][0]);
            atomicAdd(&On[(size_t)(cb2 + 1) * HW + row_a], o[j][1]);
            atomicAdd(&On[(size_t)cb2 * HW + row_b], o[j][2]);
            atomicAdd(&On[(size_t)(cb2 + 1) * HW + row_b], o[j][3]);
        }

        u = (qt << 6) + kvend;
    }
}

extern "C" void kernel_launch(void* const* d_in, const int* in_sizes, int n_in,
                              void* d_out, int out_size) {
    const float* X = (const float*)d_in[0];
    float* out = (float*)d_out;
    cudaFuncSetAttribute(attn_mma, cudaFuncAttributeMaxDynamicSharedMemorySize, SMEM_TOTAL);
    zero_kernel<<<2048 + 32, 256>>>(out);                  // out + lacc = 0
    convert_kernel<<<(NB * CD * HW / 4) / 256, 256>>>(X);
    norm_kernel<<<dim3(HW / 256, NB), 256>>>(X);
    attn_mma<<<NCTA, 128, SMEM_TOTAL>>>(out);
    final_kernel<<<(NB * CD * HW) / 256, 256>>>(out);
}

// round 16
// speedup vs baseline: 1.0468x; 1.0227x over previous
#include <cuda_runtime.h>
#include <cuda_fp16.h>
#include <cstdint>

#define HW 4096
#define CD 64
#define BM 64
#define BN 64
#define NB 8
#define NCTA 444                 // 3 x 148 -> one uniform wave at 3 CTAs/SM
#define RB 72
#define RBB (RB * 2)             // 144
#define HALF_BYTES (64 * RBB)    // 9216
#define KVBUF (2 * HALF_BYTES)   // 18432
#define SMEM_TOTAL (4 * KVBUF)   // 73728 -> 3 CTAs/SM (221KB of 227KB)
#define L2E 1.4426950408889634f

__device__ __align__(16) __half g_FH[NB * CD * HW];
__device__ __align__(16) __half g_FL[NB * CD * HW];
__device__ float g_negM[NB * HW];   // -(||x_q||^2 + 1) * log2(e)
__device__ float g_lacc[NB * HW];   // softmax denominator accumulator

__device__ __forceinline__ uint32_t smem_u32(const void* p) {
    uint32_t a;
    asm("{ .reg .u64 t; cvta.to.shared.u64 t, %1; cvt.u32.u64 %0, t; }" : "=r"(a) : "l"(p));
    return a;
}
__device__ __forceinline__ void ldsm4(uint32_t addr, uint32_t* r) {
    asm volatile("ldmatrix.sync.aligned.m8n8.x4.shared.b16 {%0,%1,%2,%3}, [%4];"
                 : "=r"(r[0]), "=r"(r[1]), "=r"(r[2]), "=r"(r[3]) : "r"(addr));
}
__device__ __forceinline__ void ldsm4t(uint32_t addr, uint32_t* r) {
    asm volatile("ldmatrix.sync.aligned.m8n8.x4.trans.shared.b16 {%0,%1,%2,%3}, [%4];"
                 : "=r"(r[0]), "=r"(r[1]), "=r"(r[2]), "=r"(r[3]) : "r"(addr));
}
__device__ __forceinline__ void mma_f16(float* d, const uint32_t* a, uint32_t b0, uint32_t b1) {
    asm volatile(
        "mma.sync.aligned.m16n8k16.row.col.f32.f16.f16.f32 "
        "{%0,%1,%2,%3}, {%4,%5,%6,%7}, {%8,%9}, {%0,%1,%2,%3};"
        : "+f"(d[0]), "+f"(d[1]), "+f"(d[2]), "+f"(d[3])
        : "r"(a[0]), "r"(a[1]), "r"(a[2]), "r"(a[3]), "r"(b0), "r"(b1));
}
#define CP16(dst, src) asm volatile("cp.async.cg.shared.global [%0], [%1], 16;" :: "r"(dst), "l"(src))
#define CP_COMMIT()    asm volatile("cp.async.commit_group;" ::: "memory")
#define CP_WAIT1()     asm volatile("cp.async.wait_group 1;" ::: "memory")
#define CP_WAIT2()     asm volatile("cp.async.wait_group 2;" ::: "memory")

__device__ __forceinline__ uint32_t pkf16(float a, float b) {
    uint32_t r;
    asm("cvt.rn.f16x2.f32 %0, %1, %2;" : "=r"(r) : "f"(b), "f"(a));
    return r;
}
__device__ __forceinline__ float ex2(float x) {
    float r;
    asm("ex2.approx.ftz.f32 %0, %1;" : "=f"(r) : "f"(x));
    return r;
}

// ---------------- pre-kernel 0: zero out-accumulator and l-accumulator ----------------
__global__ __launch_bounds__(256) void zero_kernel(float* __restrict__ out) {
    int b = blockIdx.x;
    int i = b * 256 + threadIdx.x;
    if (b < 2048) {
        reinterpret_cast<float4*>(out)[i] = make_float4(0.f, 0.f, 0.f, 0.f);
    } else {
        int j = i - 2048 * 256;
        reinterpret_cast<float4*>(g_lacc)[j] = make_float4(0.f, 0.f, 0.f, 0.f);
    }
}

// ---------------- pre-kernel 1: split X into fp16 hi/lo ----------------
__global__ __launch_bounds__(256) void convert_kernel(const float* __restrict__ X) {
    size_t i = (size_t)blockIdx.x * 256 + threadIdx.x;
    float4 v = reinterpret_cast<const float4*>(X)[i];
    __half hx = __float2half_rn(v.x), hy = __float2half_rn(v.y);
    __half hz = __float2half_rn(v.z), hw = __float2half_rn(v.w);
    __half lx = __float2half_rn(v.x - __half2float(hx));
    __half ly = __float2half_rn(v.y - __half2float(hy));
    __half lz = __float2half_rn(v.z - __half2float(hz));
    __half lw = __float2half_rn(v.w - __half2float(hw));
    uint2 h, l;
    h.x = (uint32_t)__half_as_ushort(hx) | ((uint32_t)__half_as_ushort(hy) << 16);
    h.y = (uint32_t)__half_as_ushort(hz) | ((uint32_t)__half_as_ushort(hw) << 16);
    l.x = (uint32_t)__half_as_ushort(lx) | ((uint32_t)__half_as_ushort(ly) << 16);
    l.y = (uint32_t)__half_as_ushort(lz) | ((uint32_t)__half_as_ushort(lw) << 16);
    reinterpret_cast<uint2*>(g_FH)[i] = h;
    reinterpret_cast<uint2*>(g_FL)[i] = l;
}

// ---------------- pre-kernel 2: diagonal softmax shift ----------------
__global__ __launch_bounds__(256) void norm_kernel(const float* __restrict__ X) {
    const int n = blockIdx.y;
    const int q = blockIdx.x * 256 + threadIdx.x;
    const float* Xn = X + (size_t)n * CD * HW;
    float s = 0.f;
#pragma unroll
    for (int c = 0; c < CD; c++) {
        float v = Xn[c * HW + q];
        s = fmaf(v, v, s);
    }
    g_negM[n * HW + q] = -(s + 1.0f) * L2E;
}

// ---------------- post-kernel: normalize ----------------
__global__ __launch_bounds__(256) void final_kernel(float* __restrict__ out) {
    int idx = blockIdx.x * 256 + threadIdx.x;
    int q = idx & (HW - 1);
    int n = idx >> 18;
    out[idx] *= 1.0f / g_lacc[n * HW + q];
}

// ---------------- main attention kernel: 444 uniform tasks, deferred gemm2 ----------------
__global__ __launch_bounds__(128, 3) void attn_mma(float* __restrict__ out) {
    extern __shared__ __align__(128) char SM[];
    const uint32_t smb = smem_u32(SM);

    const int tid = threadIdx.x;
    const int lane = tid & 31;
    const int wid = tid >> 5;
    const int g = lane >> 2, tq = lane & 3;
    const int r8 = lane & 7, sel = lane >> 3;

    const uint32_t g1off = ((sel & 1) * 8 + r8) * RBB + ((sel >> 1) * 8) * 2;
    const uint32_t g2off = ((sel >> 1) * 8 + r8) * RBB + ((sel & 1) * 8) * 2;

    const int k = blockIdx.x;
    int u = (k * 8192) / 111;                 // 32768*k/444
    const int uend = ((k + 1) * 8192) / 111;

    while (u < uend) {
        const int qt = u >> 6;
        const int n = qt >> 6;
        const int q0 = (qt & 63) * BM;
        const int kv0 = u & 63;
        const int kvend = min(uend - (qt << 6), 64);
        const int cnt = kvend - kv0;

        const char* FHn = (const char*)(g_FH + (size_t)n * CD * HW);
        const char* FLn = (const char*)(g_FL + (size_t)n * CD * HW);

        auto stage = [&](int buf, int col0) {
            const uint32_t bufoff = (uint32_t)buf * KVBUF;
#pragma unroll
            for (int i = 0; i < 8; i++) {
                int idx = i * 128 + tid;
                int half = idx >> 9;
                int c = (idx >> 3) & 63;
                int ch = idx & 7;
                const char* base = half ? FLn : FHn;
                const char* src = base + ((size_t)c * HW + col0 + ch * 8) * 2;
                uint32_t dst = smb + bufoff + half * HALF_BYTES + c * RBB + ch * 16;
                CP16(dst, src);
            }
        };

        // ---- segment prologue ----
        __syncthreads();                     // previous segment's reads fully done
        stage(3, q0);                        // Q -> buf3 (freed after frag extraction)
        CP_COMMIT();
        stage(0, (kv0 + 0) * BN);
        CP_COMMIT();
        if (cnt > 1) stage(1, (kv0 + 1) * BN);
        CP_COMMIT();
        CP_WAIT2();                          // Q group done
        __syncthreads();
        uint32_t qh[4][4], ql[4][4];
        {
            const uint32_t qb = smb + 3 * KVBUF;
            const uint32_t lo = ((sel >> 1) * 8 + r8) * RBB + (wid * 16 + (sel & 1) * 8) * 2;
#pragma unroll
            for (int ch = 0; ch < 4; ch++) {
                ldsm4t(qb + ch * 16 * RBB + lo, qh[ch]);
                ldsm4t(qb + HALF_BYTES + ch * 16 * RBB + lo, ql[ch]);
            }
        }
        const int row_a = wid * 16 + g, row_b = row_a + 8;
        const float negMa = g_negM[n * HW + q0 + row_a];
        const float negMb = g_negM[n * HW + q0 + row_b];

        float o[8][4];
#pragma unroll
        for (int j = 0; j < 8; j++)
#pragma unroll
            for (int r = 0; r < 4; r++) o[j][r] = 0.f;
        float la = 0.f, lb = 0.f;
        uint32_t pfp[4][4];                  // P fragments of tile i-1 (deferred gemm2)

        // gemm2 of one lagging tile (buf vb2, fragments pfp)
        auto gemm2run = [&](uint32_t vb2) {
#pragma unroll
            for (int kc = 0; kc < 4; kc++) {
#pragma unroll
                for (int mp = 0; mp < 2; mp++) {
                    const uint32_t ba = vb2 + g2off + (2 * mp) * 16 * RBB + kc * 32;
                    const uint32_t bb = ba + 16 * RBB;
                    uint32_t bfa[4], bfb[4];
                    ldsm4(ba, bfa);
                    ldsm4(bb, bfb);
                    mma_f16(o[4 * mp], pfp[kc], bfa[0], bfa[1]);
                    mma_f16(o[4 * mp + 1], pfp[kc], bfa[2], bfa[3]);
                    mma_f16(o[4 * mp + 2], pfp[kc], bfb[0], bfb[1]);
                    mma_f16(o[4 * mp + 3], pfp[kc], bfb[2], bfb[3]);
                }
            }
        };

        for (int i = 0; i < cnt; i++) {
            CP_WAIT1();                      // tile i resident
            __syncthreads();                 // all warps done iter i-1 (frees buf (i+2)&3)
            if (i + 2 < cnt) stage((i + 2) & 3, (kv0 + i + 2) * BN);
            CP_COMMIT();
            const uint32_t vb = smb + ((uint32_t)(i & 3)) * KVBUF;

            // ---- gemm1: S(16x64) = Q Kt, fp16 3 split passes ----
            float s[8][4];
#pragma unroll
            for (int j = 0; j < 8; j++)
#pragma unroll
                for (int r = 0; r < 4; r++) s[j][r] = 0.f;
#pragma unroll
            for (int ch = 0; ch < 4; ch++) {
                const uint32_t base = vb + g1off + ch * 16 * RBB;
#pragma unroll
                for (int kp = 0; kp < 2; kp++) {
                    const uint32_t ka = base + (2 * kp) * 32;
                    const uint32_t kb = ka + 32;
                    uint32_t bh0[4], bl0[4], bh1[4], bl1[4];
                    ldsm4t(ka, bh0);
                    ldsm4t(ka + HALF_BYTES, bl0);
                    ldsm4t(kb, bh1);
                    ldsm4t(kb + HALF_BYTES, bl1);
                    float* s0 = s[4 * kp], * s1 = s[4 * kp + 1];
                    float* s2 = s[4 * kp + 2], * s3 = s[4 * kp + 3];
                    mma_f16(s0, qh[ch], bh0[0], bh0[1]);
                    mma_f16(s1, qh[ch], bh0[2], bh0[3]);
                    mma_f16(s2, qh[ch], bh1[0], bh1[1]);
                    mma_f16(s3, qh[ch], bh1[2], bh1[3]);
                    mma_f16(s0, qh[ch], bl0[0], bl0[1]);
                    mma_f16(s1, qh[ch], bl0[2], bl0[3]);
                    mma_f16(s2, qh[ch], bl1[0], bl1[1]);
                    mma_f16(s3, qh[ch], bl1[2], bl1[3]);
                    mma_f16(s0, ql[ch], bh0[0], bh0[1]);
                    mma_f16(s1, ql[ch], bh0[2], bh0[3]);
                    mma_f16(s2, ql[ch], bh1[0], bh1[1]);
                    mma_f16(s3, ql[ch], bh1[2], bh1[3]);
                }
            }

            // ---- deferred gemm2(i-1): independent MMAs to overlap softmax(i) ----
            if (i > 0) gemm2run(smb + ((uint32_t)((i - 1) & 3)) * KVBUF);

            // ---- static-shift softmax(i): s -> pfp ----
#pragma unroll
            for (int kc = 0; kc < 4; kc++) {
                float e0 = ex2(fmaf(s[2 * kc][0], L2E, negMa));
                float e1 = ex2(fmaf(s[2 * kc][1], L2E, negMa));
                float e2 = ex2(fmaf(s[2 * kc][2], L2E, negMb));
                float e3 = ex2(fmaf(s[2 * kc][3], L2E, negMb));
                float e4 = ex2(fmaf(s[2 * kc + 1][0], L2E, negMa));
                float e5 = ex2(fmaf(s[2 * kc + 1][1], L2E, negMa));
                float e6 = ex2(fmaf(s[2 * kc + 1][2], L2E, negMb));
                float e7 = ex2(fmaf(s[2 * kc + 1][3], L2E, negMb));
                la += e0 + e1 + e4 + e5;
                lb += e2 + e3 + e6 + e7;
                pfp[kc][0] = pkf16(e0, e1);
                pfp[kc][1] = pkf16(e2, e3);
                pfp[kc][2] = pkf16(e4, e5);
                pfp[kc][3] = pkf16(e6, e7);
            }
        }
        // ---- drain: gemm2 of the segment's last tile ----
        gemm2run(smb + ((uint32_t)((cnt - 1) & 3)) * KVBUF);

        // ---- flush partial O and l (additive under the static shift) ----
        la += __shfl_xor_sync(~0u, la, 1);
        la += __shfl_xor_sync(~0u, la, 2);
        lb += __shfl_xor_sync(~0u, lb, 1);
        lb += __shfl_xor_sync(~0u, lb, 2);
        if (tq == 0) {
            atomicAdd(&g_lacc[n * HW + q0 + row_a], la);
            atomicAdd(&g_lacc[n * HW + q0 + row_b], lb);
        }
        float* On = out + (size_t)n * CD * HW + q0;
#pragma unroll
        for (int j = 0; j < 8; j++) {
            int cb2 = j * 8 + 2 * tq;
            atomicAdd(&On[(size_t)cb2 * HW + row_a], o[j][0]);
            atomicAdd(&On[(size_t)(cb2 + 1) * HW + row_a], o[j][1]);
            atomicAdd(&On[(size_t)cb2 * HW + row_b], o[j][2]);
            atomicAdd(&On[(size_t)(cb2 + 1) * HW + row_b], o[j][3]);
        }

        u = (qt << 6) + kvend;
    }
}

extern "C" void kernel_launch(void* const* d_in, const int* in_sizes, int n_in,
                              void* d_out, int out_size) {
    const float* X = (const float*)d_in[0];
    float* out = (float*)d_out;
    cudaFuncSetAttribute(attn_mma, cudaFuncAttributeMaxDynamicSharedMemorySize, SMEM_TOTAL);
    zero_kernel<<<2048 + 32, 256>>>(out);
    convert_kernel<<<(NB * CD * HW / 4) / 256, 256>>>(X);
    norm_kernel<<<dim3(HW / 256, NB), 256>>>(X);
    attn_mma<<<NCTA, 128, SMEM_TOTAL>>>(out);
    final_kernel<<<(NB * CD * HW) / 256, 256>>>(out);
}

// round 17
// speedup vs baseline: 1.0765x; 1.0284x over previous
#include <cuda_runtime.h>
#include <cuda_fp16.h>
#include <cstdint>

#define HW 4096
#define CD 64
#define BM 64
#define BN 64
#define NB 8
#define NCTA 444                 // 3 x 148 -> one uniform wave at 3 CTAs/SM
#define RB 72
#define RBB (RB * 2)             // 144
#define HALF_BYTES (64 * RBB)    // 9216
#define KVBUF (2 * HALF_BYTES)   // 18432
#define SMEM_TOTAL (4 * KVBUF)   // 73728 -> 3 CTAs/SM
#define L2E 1.4426950408889634f

__device__ __align__(16) __half g_FH[NB * CD * HW];
__device__ __align__(16) __half g_FL[NB * CD * HW];
__device__ float g_negM[NB * HW];   // -(||x_q||^2 + 1) * log2(e)
__device__ float g_lacc[NB * HW];   // softmax denominator accumulator

__device__ __forceinline__ uint32_t smem_u32(const void* p) {
    uint32_t a;
    asm("{ .reg .u64 t; cvta.to.shared.u64 t, %1; cvt.u32.u64 %0, t; }" : "=r"(a) : "l"(p));
    return a;
}
__device__ __forceinline__ void ldsm4(uint32_t addr, uint32_t* r) {
    asm volatile("ldmatrix.sync.aligned.m8n8.x4.shared.b16 {%0,%1,%2,%3}, [%4];"
                 : "=r"(r[0]), "=r"(r[1]), "=r"(r[2]), "=r"(r[3]) : "r"(addr));
}
__device__ __forceinline__ void ldsm4t(uint32_t addr, uint32_t* r) {
    asm volatile("ldmatrix.sync.aligned.m8n8.x4.trans.shared.b16 {%0,%1,%2,%3}, [%4];"
                 : "=r"(r[0]), "=r"(r[1]), "=r"(r[2]), "=r"(r[3]) : "r"(addr));
}
__device__ __forceinline__ void mma_f16(float* d, const uint32_t* a, uint32_t b0, uint32_t b1) {
    asm volatile(
        "mma.sync.aligned.m16n8k16.row.col.f32.f16.f16.f32 "
        "{%0,%1,%2,%3}, {%4,%5,%6,%7}, {%8,%9}, {%0,%1,%2,%3};"
        : "+f"(d[0]), "+f"(d[1]), "+f"(d[2]), "+f"(d[3])
        : "r"(a[0]), "r"(a[1]), "r"(a[2]), "r"(a[3]), "r"(b0), "r"(b1));
}
#define CP16(dst, src) asm volatile("cp.async.cg.shared.global [%0], [%1], 16;" :: "r"(dst), "l"(src))
#define CP_COMMIT()    asm volatile("cp.async.commit_group;" ::: "memory")
#define CP_WAIT1()     asm volatile("cp.async.wait_group 1;" ::: "memory")
#define CP_WAIT2()     asm volatile("cp.async.wait_group 2;" ::: "memory")

__device__ __forceinline__ uint32_t pkf16(float a, float b) {
    uint32_t r;
    asm("cvt.rn.f16x2.f32 %0, %1, %2;" : "=r"(r) : "f"(b), "f"(a));
    return r;
}
__device__ __forceinline__ float ex2(float x) {
    float r;
    asm("ex2.approx.ftz.f32 %0, %1;" : "=f"(r) : "f"(x));
    return r;
}

// ---- pre-kernel 1: split X into fp16 hi/lo; also zero out-accum and l-accum ----
__global__ __launch_bounds__(256) void convert_kernel(const float* __restrict__ X,
                                                      float* __restrict__ out) {
    size_t i = (size_t)blockIdx.x * 256 + threadIdx.x;
    float4 v = reinterpret_cast<const float4*>(X)[i];
    __half hx = __float2half_rn(v.x), hy = __float2half_rn(v.y);
    __half hz = __float2half_rn(v.z), hw = __float2half_rn(v.w);
    __half lx = __float2half_rn(v.x - __half2float(hx));
    __half ly = __float2half_rn(v.y - __half2float(hy));
    __half lz = __float2half_rn(v.z - __half2float(hz));
    __half lw = __float2half_rn(v.w - __half2float(hw));
    uint2 h, l;
    h.x = (uint32_t)__half_as_ushort(hx) | ((uint32_t)__half_as_ushort(hy) << 16);
    h.y = (uint32_t)__half_as_ushort(hz) | ((uint32_t)__half_as_ushort(hw) << 16);
    l.x = (uint32_t)__half_as_ushort(lx) | ((uint32_t)__half_as_ushort(ly) << 16);
    l.y = (uint32_t)__half_as_ushort(lz) | ((uint32_t)__half_as_ushort(lw) << 16);
    reinterpret_cast<uint2*>(g_FH)[i] = h;
    reinterpret_cast<uint2*>(g_FL)[i] = l;
    // zero the accumulators (graph-replay safe: re-zeroed every launch)
    reinterpret_cast<float4*>(out)[i] = make_float4(0.f, 0.f, 0.f, 0.f);
    if (i < (NB * HW) / 4)
        reinterpret_cast<float4*>(g_lacc)[i] = make_float4(0.f, 0.f, 0.f, 0.f);
}

// ---- pre-kernel 2: diagonal softmax shift ----
__global__ __launch_bounds__(256) void norm_kernel(const float* __restrict__ X) {
    const int n = blockIdx.y;
    const int q = blockIdx.x * 256 + threadIdx.x;
    const float* Xn = X + (size_t)n * CD * HW;
    float s = 0.f;
#pragma unroll
    for (int c = 0; c < CD; c++) {
        float v = Xn[c * HW + q];
        s = fmaf(v, v, s);
    }
    g_negM[n * HW + q] = -(s + 1.0f) * L2E;
}

// ---- post-kernel: normalize (vectorized) ----
__global__ __launch_bounds__(256) void final_kernel(float* __restrict__ out) {
    int i4 = blockIdx.x * 256 + threadIdx.x;        // over NB*CD*HW/4
    int idx = i4 * 4;
    int q = idx & (HW - 1);
    int n = idx >> 18;
    float4 lv = *reinterpret_cast<const float4*>(&g_lacc[n * HW + q]);
    float4 ov = reinterpret_cast<float4*>(out)[i4];
    ov.x *= 1.0f / lv.x;
    ov.y *= 1.0f / lv.y;
    ov.z *= 1.0f / lv.z;
    ov.w *= 1.0f / lv.w;
    reinterpret_cast<float4*>(out)[i4] = ov;
}

// ---- main attention kernel: 444 uniform tasks, deferred gemm2 ----
__global__ __launch_bounds__(128, 3) void attn_mma(float* __restrict__ out) {
    extern __shared__ __align__(128) char SM[];
    const uint32_t smb = smem_u32(SM);

    const int tid = threadIdx.x;
    const int lane = tid & 31;
    const int wid = tid >> 5;
    const int g = lane >> 2, tq = lane & 3;
    const int r8 = lane & 7, sel = lane >> 3;

    const uint32_t g1off = ((sel & 1) * 8 + r8) * RBB + ((sel >> 1) * 8) * 2;
    const uint32_t g2off = ((sel >> 1) * 8 + r8) * RBB + ((sel & 1) * 8) * 2;

    const int k = blockIdx.x;
    int u = (k * 8192) / 111;
    const int uend = ((k + 1) * 8192) / 111;

    while (u < uend) {
        const int qt = u >> 6;
        const int n = qt >> 6;
        const int q0 = (qt & 63) * BM;
        const int kv0 = u & 63;
        const int kvend = min(uend - (qt << 6), 64);
        const int cnt = kvend - kv0;

        const char* FHn = (const char*)(g_FH + (size_t)n * CD * HW);
        const char* FLn = (const char*)(g_FL + (size_t)n * CD * HW);

        auto stage = [&](int buf, int col0) {
            const uint32_t bufoff = (uint32_t)buf * KVBUF;
#pragma unroll
            for (int i = 0; i < 8; i++) {
                int idx = i * 128 + tid;
                int half = idx >> 9;
                int c = (idx >> 3) & 63;
                int ch = idx & 7;
                const char* base = half ? FLn : FHn;
                const char* src = base + ((size_t)c * HW + col0 + ch * 8) * 2;
                uint32_t dst = smb + bufoff + half * HALF_BYTES + c * RBB + ch * 16;
                CP16(dst, src);
            }
        };

        // ---- segment prologue ----
        __syncthreads();                     // previous segment's reads fully done
        stage(3, q0);                        // Q -> buf3 (freed after frag extraction)
        CP_COMMIT();
        stage(0, (kv0 + 0) * BN);
        CP_COMMIT();
        if (cnt > 1) stage(1, (kv0 + 1) * BN);
        CP_COMMIT();
        CP_WAIT2();                          // Q group done
        __syncthreads();
        uint32_t qh[4][4], ql[4][4];
        {
            const uint32_t qb = smb + 3 * KVBUF;
            const uint32_t lo = ((sel >> 1) * 8 + r8) * RBB + (wid * 16 + (sel & 1) * 8) * 2;
#pragma unroll
            for (int ch = 0; ch < 4; ch++) {
                ldsm4t(qb + ch * 16 * RBB + lo, qh[ch]);
                ldsm4t(qb + HALF_BYTES + ch * 16 * RBB + lo, ql[ch]);
            }
        }
        const int row_a = wid * 16 + g, row_b = row_a + 8;
        const float negMa = g_negM[n * HW + q0 + row_a];
        const float negMb = g_negM[n * HW + q0 + row_b];

        float o[8][4];
#pragma unroll
        for (int j = 0; j < 8; j++)
#pragma unroll
            for (int r = 0; r < 4; r++) o[j][r] = 0.f;
        float la = 0.f, lb = 0.f;
        uint32_t pfp[4][4];                  // P fragments of tile i-1 (deferred gemm2)

        auto gemm2run = [&](uint32_t vb2) {
#pragma unroll
            for (int kc = 0; kc < 4; kc++) {
#pragma unroll
                for (int mp = 0; mp < 2; mp++) {
                    const uint32_t ba = vb2 + g2off + (2 * mp) * 16 * RBB + kc * 32;
                    const uint32_t bb = ba + 16 * RBB;
                    uint32_t bfa[4], bfb[4];
                    ldsm4(ba, bfa);
                    ldsm4(bb, bfb);
                    mma_f16(o[4 * mp], pfp[kc], bfa[0], bfa[1]);
                    mma_f16(o[4 * mp + 1], pfp[kc], bfa[2], bfa[3]);
                    mma_f16(o[4 * mp + 2], pfp[kc], bfb[0], bfb[1]);
                    mma_f16(o[4 * mp + 3], pfp[kc], bfb[2], bfb[3]);
                }
            }
        };

        for (int i = 0; i < cnt; i++) {
            CP_WAIT1();                      // tile i resident
            __syncthreads();                 // all warps done iter i-1 (frees buf (i+2)&3)
            if (i + 2 < cnt) stage((i + 2) & 3, (kv0 + i + 2) * BN);
            CP_COMMIT();
            const uint32_t vb = smb + ((uint32_t)(i & 3)) * KVBUF;

            // ---- gemm1: S(16x64) = Q Kt, fp16 3 split passes ----
            float s[8][4];
#pragma unroll
            for (int j = 0; j < 8; j++)
#pragma unroll
                for (int r = 0; r < 4; r++) s[j][r] = 0.f;
#pragma unroll
            for (int ch = 0; ch < 4; ch++) {
                const uint32_t base = vb + g1off + ch * 16 * RBB;
#pragma unroll
                for (int kp = 0; kp < 2; kp++) {
                    const uint32_t ka = base + (2 * kp) * 32;
                    const uint32_t kb = ka + 32;
                    uint32_t bh0[4], bl0[4], bh1[4], bl1[4];
                    ldsm4t(ka, bh0);
                    ldsm4t(ka + HALF_BYTES, bl0);
                    ldsm4t(kb, bh1);
                    ldsm4t(kb + HALF_BYTES, bl1);
                    float* s0 = s[4 * kp], * s1 = s[4 * kp + 1];
                    float* s2 = s[4 * kp + 2], * s3 = s[4 * kp + 3];
                    mma_f16(s0, qh[ch], bh0[0], bh0[1]);
                    mma_f16(s1, qh[ch], bh0[2], bh0[3]);
                    mma_f16(s2, qh[ch], bh1[0], bh1[1]);
                    mma_f16(s3, qh[ch], bh1[2], bh1[3]);
                    mma_f16(s0, qh[ch], bl0[0], bl0[1]);
                    mma_f16(s1, qh[ch], bl0[2], bl0[3]);
                    mma_f16(s2, qh[ch], bl1[0], bl1[1]);
                    mma_f16(s3, qh[ch], bl1[2], bl1[3]);
                    mma_f16(s0, ql[ch], bh0[0], bh0[1]);
                    mma_f16(s1, ql[ch], bh0[2], bh0[3]);
                    mma_f16(s2, ql[ch], bh1[0], bh1[1]);
                    mma_f16(s3, ql[ch], bh1[2], bh1[3]);
                }
            }

            // ---- deferred gemm2(i-1): independent MMAs overlap softmax(i) ----
            if (i > 0) gemm2run(smb + ((uint32_t)((i - 1) & 3)) * KVBUF);

            // ---- static-shift softmax(i): s -> pfp ----
#pragma unroll
            for (int kc = 0; kc < 4; kc++) {
                float e0 = ex2(fmaf(s[2 * kc][0], L2E, negMa));
                float e1 = ex2(fmaf(s[2 * kc][1], L2E, negMa));
                float e2 = ex2(fmaf(s[2 * kc][2], L2E, negMb));
                float e3 = ex2(fmaf(s[2 * kc][3], L2E, negMb));
                float e4 = ex2(fmaf(s[2 * kc + 1][0], L2E, negMa));
                float e5 = ex2(fmaf(s[2 * kc + 1][1], L2E, negMa));
                float e6 = ex2(fmaf(s[2 * kc + 1][2], L2E, negMb));
                float e7 = ex2(fmaf(s[2 * kc + 1][3], L2E, negMb));
                la += e0 + e1 + e4 + e5;
                lb += e2 + e3 + e6 + e7;
                pfp[kc][0] = pkf16(e0, e1);
                pfp[kc][1] = pkf16(e2, e3);
                pfp[kc][2] = pkf16(e4, e5);
                pfp[kc][3] = pkf16(e6, e7);
            }
        }
        // ---- drain: gemm2 of the segment's last tile ----
        gemm2run(smb + ((uint32_t)((cnt - 1) & 3)) * KVBUF);

        // ---- flush partial O and l (additive under the static shift) ----
        la += __shfl_xor_sync(~0u, la, 1);
        la += __shfl_xor_sync(~0u, la, 2);
        lb += __shfl_xor_sync(~0u, lb, 1);
        lb += __shfl_xor_sync(~0u, lb, 2);
        if (tq == 0) {
            atomicAdd(&g_lacc[n * HW + q0 + row_a], la);
            atomicAdd(&g_lacc[n * HW + q0 + row_b], lb);
        }
        float* On = out + (size_t)n * CD * HW + q0;
#pragma unroll
        for (int j = 0; j < 8; j++) {
            int cb2 = j * 8 + 2 * tq;
            atomicAdd(&On[(size_t)cb2 * HW + row_a], o[j][0]);
            atomicAdd(&On[(size_t)(cb2 + 1) * HW + row_a], o[j][1]);
            atomicAdd(&On[(size_t)cb2 * HW + row_b], o[j][2]);
            atomicAdd(&On[(size_t)(cb2 + 1) * HW + row_b], o[j][3]);
        }

        u = (qt << 6) + kvend;
    }
}

extern "C" void kernel_launch(void* const* d_in, const int* in_sizes, int n_in,
                              void* d_out, int out_size) {
    const float* X = (const float*)d_in[0];
    float* out = (float*)d_out;
    cudaFuncSetAttribute(attn_mma, cudaFuncAttributeMaxDynamicSharedMemorySize, SMEM_TOTAL);
    convert_kernel<<<(NB * CD * HW / 4) / 256, 256>>>(X, out);   // also zeroes out + lacc
    norm_kernel<<<dim3(HW / 256, NB), 256>>>(X);
    attn_mma<<<NCTA, 128, SMEM_TOTAL>>>(out);
    final_kernel<<<(NB * CD * HW / 4) / 256, 256>>>(out);
}